// round 5
// baseline (speedup 1.0000x reference)
#include <cuda_runtime.h>
#include <cstdint>

// Problem constants
constexpr int Bn  = 8;
constexpr int Ss  = 4096;
constexpr int Dd  = 640;
constexpr int Tt  = 77;
constexpr int DEe = 768;
constexpr int Hh  = 10;
constexpr int HDd = 64;
constexpr int Rr  = 64;
constexpr int KB  = 768;   // fused final-GEMM K = Dd + 2*Rr
constexpr float LN_EPS = 1e-5f;

// ---------------- scratch (static device globals; no allocation) ----------------
__device__ float g_q   [(size_t)Bn*Ss*Dd];
__device__ float g_k   [(size_t)Bn*Tt*Dd];
__device__ float g_v   [(size_t)Bn*Tt*Dd];
__device__ float g_F0  [(size_t)Bn*Ss*Dd];
__device__ float g_F1  [(size_t)Bn*Ss*Dd];
__device__ float g_Abig[(size_t)Bn*Ss*KB];   // [G | h0 | h1]
__device__ float g_Wbig[(size_t)Dd*KB];      // [Wo | c1*M0 | c1*M1]
__device__ float g_bo2 [Dd];

// ================= TF32 tensor-core GEMM: C[m,n] = sum_k A[m,k]*W[n,k] (+bias) ==
// 128x128 block tile, BK=32, 8 warps of 64x32 warp tiles, mma.sync.m16n8k8.tf32.
// Two-stage smem ping-pong, streaming staging (low register pressure), target
// 2 blocks/SM for latency hiding.
constexpr int GLDA = 36;   // smem row stride (32 + 4 pad)
constexpr int GEMM_STAGE = 128 * GLDA;             // floats per matrix per stage
constexpr int GEMM_SMEM_BYTES = 2 * 2 * GEMM_STAGE * 4;  // 73728

__device__ __forceinline__ uint32_t f2tf32(float x) {
    uint32_t r;
    asm("cvt.rna.tf32.f32 %0, %1;" : "=r"(r) : "f"(x));
    return r;
}

__device__ __forceinline__ void mma_tf32(float c[4], const uint32_t a[4], const uint32_t b[2]) {
    asm volatile(
        "mma.sync.aligned.m16n8k8.row.col.f32.tf32.tf32.f32 "
        "{%0,%1,%2,%3}, {%4,%5,%6,%7}, {%8,%9}, {%0,%1,%2,%3};"
        : "+f"(c[0]), "+f"(c[1]), "+f"(c[2]), "+f"(c[3])
        : "r"(a[0]), "r"(a[1]), "r"(a[2]), "r"(a[3]), "r"(b[0]), "r"(b[1]));
}

template<bool HAS_BIAS, bool FULL>
__global__ __launch_bounds__(256, 2)
void gemm_tf32_kernel(const float* __restrict__ A, const float* __restrict__ W,
                      const float* __restrict__ bias, float* __restrict__ C,
                      int M, int N, int K)
{
    extern __shared__ uint32_t smem_u[];
    uint32_t* AsBase = smem_u;                 // [stage][128*GLDA]
    uint32_t* BsBase = smem_u + GEMM_STAGE;

    const int tid  = threadIdx.x;
    const int wid  = tid >> 5;
    const int lane = tid & 31;
    const int g    = lane >> 2;
    const int tg   = lane & 3;

    const int m0 = blockIdx.y * 128;
    const int n0 = blockIdx.x * 128;
    const int wm = (wid & 1) * 64;
    const int wn = (wid >> 1) * 32;

    const int ldrow = tid >> 3;        // 0..31 base row (x4 pages)
    const int ldseg = tid & 7;         // float4 segment within 32-k row

    float acc[4][4][4];
#pragma unroll
    for (int i = 0; i < 4; i++)
#pragma unroll
        for (int j = 0; j < 4; j++)
#pragma unroll
            for (int r = 0; r < 4; r++) acc[i][j][r] = 0.f;

    // streaming staging: load -> cvt -> store to given stage (few live regs)
    auto stage_tile = [&](int k0, int stage) {
        uint32_t* As = AsBase + stage * (2 * GEMM_STAGE);
        uint32_t* Bs = BsBase + stage * (2 * GEMM_STAGE);
#pragma unroll
        for (int p = 0; p < 4; p++) {
            const int row = ldrow + p * 32;
            float4 va = make_float4(0.f, 0.f, 0.f, 0.f);
            float4 vb = make_float4(0.f, 0.f, 0.f, 0.f);
            if (FULL) {
                va = *(const float4*)(A + (size_t)(m0 + row) * K + k0 + ldseg * 4);
                vb = *(const float4*)(W + (size_t)(n0 + row) * K + k0 + ldseg * 4);
            } else {
                if (m0 + row < M) va = *(const float4*)(A + (size_t)(m0 + row) * K + k0 + ldseg * 4);
                if (n0 + row < N) vb = *(const float4*)(W + (size_t)(n0 + row) * K + k0 + ldseg * 4);
            }
            uint4 ta, tb;
            ta.x = f2tf32(va.x); ta.y = f2tf32(va.y); ta.z = f2tf32(va.z); ta.w = f2tf32(va.w);
            tb.x = f2tf32(vb.x); tb.y = f2tf32(vb.y); tb.z = f2tf32(vb.z); tb.w = f2tf32(vb.w);
            *(uint4*)&As[row * GLDA + ldseg * 4] = ta;
            *(uint4*)&Bs[row * GLDA + ldseg * 4] = tb;
        }
    };

    stage_tile(0, 0);

    int cur = 0;
    for (int k0 = 0; k0 < K; k0 += 32) {
        __syncthreads();   // stage 'cur' visible; prior reads of 'cur^1' done

        if (k0 + 32 < K) stage_tile(k0 + 32, cur ^ 1);  // fill idle buffer

        const uint32_t* As = AsBase + cur * (2 * GEMM_STAGE);
        const uint32_t* Bs = BsBase + cur * (2 * GEMM_STAGE);
#pragma unroll
        for (int ka = 0; ka < 4; ka++) {
            const int kc = ka * 8;
            uint32_t afr[4][4];
            uint32_t bfr[4][2];
#pragma unroll
            for (int i = 0; i < 4; i++) {
                const int r0 = wm + 16 * i + g;
                afr[i][0] = As[r0 * GLDA + kc + tg];
                afr[i][1] = As[(r0 + 8) * GLDA + kc + tg];
                afr[i][2] = As[r0 * GLDA + kc + tg + 4];
                afr[i][3] = As[(r0 + 8) * GLDA + kc + tg + 4];
            }
#pragma unroll
            for (int j = 0; j < 4; j++) {
                const int nrow = wn + 8 * j + g;
                bfr[j][0] = Bs[nrow * GLDA + kc + tg];
                bfr[j][1] = Bs[nrow * GLDA + kc + tg + 4];
            }
#pragma unroll
            for (int i = 0; i < 4; i++)
#pragma unroll
                for (int j = 0; j < 4; j++)
                    mma_tf32(acc[i][j], afr[i], bfr[j]);
        }
        cur ^= 1;
    }

#pragma unroll
    for (int i = 0; i < 4; i++) {
        const int rowA = m0 + wm + 16 * i + g;
        const int rowB = rowA + 8;
#pragma unroll
        for (int j = 0; j < 4; j++) {
            const int col = n0 + wn + 8 * j + 2 * tg;
            float2 bv = make_float2(0.f, 0.f);
            if (HAS_BIAS) bv = *(const float2*)(bias + col);
            if (FULL || rowA < M) {
                float2 v = make_float2(acc[i][j][0] + bv.x, acc[i][j][1] + bv.y);
                *(float2*)(C + (size_t)rowA * N + col) = v;
            }
            if (FULL || rowB < M) {
                float2 v = make_float2(acc[i][j][2] + bv.x, acc[i][j][3] + bv.y);
                *(float2*)(C + (size_t)rowB * N + col) = v;
            }
        }
    }
}

// ---------------- prep: fold up-proj weights through Wo (exact fp32) ------------
// Tiled mini-GEMM. grid(80): each block handles 8 e-rows. smem-staged u chunks.
// Wbig[e,0:640]=Wo[e,:]; Wbig[e,640+r]=c1*dot(Wo[e,:],u0W[:,r]); same +704 for u1;
// bo2[e]=bo[e]+c1*dot(Wo[e,:],u0b+u1b).
constexpr int PREP_E = 8;      // e-rows per block
constexpr int PREP_DC = 64;    // d-chunk

__global__ __launch_bounds__(256)
void prep_kernel(const float* __restrict__ Wo,
                 const float* __restrict__ u0W, const float* __restrict__ u1W,
                 const float* __restrict__ u0b, const float* __restrict__ u1b,
                 const float* __restrict__ bo,  const float* __restrict__ sbr,
                 float* __restrict__ Wbig, float* __restrict__ bo2)
{
    __shared__ float sWo[PREP_E][PREP_DC];
    __shared__ float su0[PREP_DC][Rr];
    __shared__ float su1[PREP_DC][Rr];

    const int tid = threadIdx.x;
    const int e0  = blockIdx.x * PREP_E;
    const int el  = tid >> 5;          // 0..7 (e-row for compute)
    const int rl  = tid & 31;          // 0..31 (r lane; covers r and r+32)
    const float blend = 1.f / (1.f + expf(-*sbr));
    const float c1 = blend * (1.f / 3.f);

    float a00 = 0.f, a01 = 0.f, a10 = 0.f, a11 = 0.f;  // (u0,u1) x (r, r+32)

    for (int d0 = 0; d0 < Dd; d0 += PREP_DC) {
        // stage Wo tile: 8 x 64 = 512 floats
        for (int i = tid; i < PREP_E * PREP_DC; i += 256) {
            const int e = i >> 6, d = i & 63;
            sWo[e][d] = Wo[(size_t)(e0 + e) * Dd + d0 + d];
        }
        // stage u tiles: 64 x 64 each
        for (int i = tid; i < PREP_DC * Rr; i += 256) {
            const int d = i >> 6, r = i & 63;
            su0[d][r] = u0W[(size_t)(d0 + d) * Rr + r];
            su1[d][r] = u1W[(size_t)(d0 + d) * Rr + r];
        }
        __syncthreads();
#pragma unroll 8
        for (int dd = 0; dd < PREP_DC; dd++) {
            const float w = sWo[el][dd];
            a00 = fmaf(w, su0[dd][rl],      a00);
            a01 = fmaf(w, su0[dd][rl + 32], a01);
            a10 = fmaf(w, su1[dd][rl],      a10);
            a11 = fmaf(w, su1[dd][rl + 32], a11);
        }
        __syncthreads();
    }

    const int e = e0 + el;
    float* wbrow = Wbig + (size_t)e * KB;
    // write folded columns
    {
        float* dst = Wbig + (size_t)e * KB;
        dst[Dd + rl]           = c1 * a00;
        dst[Dd + rl + 32]      = c1 * a01;
        dst[Dd + Rr + rl]      = c1 * a10;
        dst[Dd + Rr + rl + 32] = c1 * a11;
    }
    // copy Wo rows into Wbig cols [0,640): 8 rows x 640, coalesced float4
    for (int i = tid; i < PREP_E * (Dd / 4); i += 256) {
        const int er = i / (Dd / 4);
        const int d4 = i % (Dd / 4);
        *(float4*)(Wbig + (size_t)(e0 + er) * KB + d4 * 4) =
            *(const float4*)(Wo + (size_t)(e0 + er) * Dd + d4 * 4);
    }
    // bias: warp el reduces dot(Wo[e,:], u0b+u1b)
    {
        float s = 0.f;
        for (int d = rl; d < Dd; d += 32)
            s = fmaf(Wo[(size_t)e * Dd + d], u0b[d] + u1b[d], s);
#pragma unroll
        for (int o = 16; o > 0; o >>= 1) s += __shfl_xor_sync(0xffffffffu, s, o);
        if (rl == 0) bo2[e] = bo[e] + c1 * s;
    }
}

// ---------------- fused attention: global + 2 entity attentions -----------------
constexpr int ATT_QT = 128;
constexpr int QPAD   = 68;
constexpr int ATT_SMEM_FLOATS = 2 * Tt * HDd + ATT_QT * QPAD + ATT_QT * Tt;

__global__ __launch_bounds__(128)
void attn_kernel(const float* __restrict__ q, const float* __restrict__ k,
                 const float* __restrict__ v,
                 const int* __restrict__ idx0, const int* __restrict__ idx1,
                 const float* __restrict__ sbr,
                 float* __restrict__ F0, float* __restrict__ F1,
                 float* __restrict__ Abig)
{
    extern __shared__ float sm[];
    float* Ksh = sm;                       // Tt*HDd
    float* Vsh = Ksh + Tt * HDd;           // Tt*HDd
    float* Qsh = Vsh + Tt * HDd;           // ATT_QT*QPAD
    float* Psh = Qsh + ATT_QT * QPAD;      // ATT_QT*Tt
    __shared__ int si0[8], si1[8];

    const int tid = threadIdx.x;
    const int b = blockIdx.y / Hh;
    const int h = blockIdx.y % Hh;
    const int s0 = blockIdx.x * ATT_QT;

    if (tid < 8) { si0[tid] = idx0[tid]; si1[tid] = idx1[tid]; }

    const float blend = 1.f / (1.f + expf(-*sbr));
    const float c1 = blend * (1.f / 3.f);
    const float c2 = 1.f - 2.f * blend * (1.f / 3.f);

    const float* kb = k + (size_t)b * Tt * Dd + h * HDd;
    const float* vb = v + (size_t)b * Tt * Dd + h * HDd;
    for (int i = tid; i < Tt * HDd; i += ATT_QT) {
        const int t = i >> 6, d = i & 63;
        Ksh[i] = kb[(size_t)t * Dd + d];
        Vsh[i] = vb[(size_t)t * Dd + d];
    }
    const float* qb = q + (size_t)(b * Ss + s0) * Dd + h * HDd;
    for (int i = tid; i < ATT_QT * HDd; i += ATT_QT) {
        const int r = i >> 6, d = i & 63;
        Qsh[r * QPAD + d] = qb[(size_t)r * Dd + d];
    }
    __syncthreads();

    {
        float4 qr[16];
        const float4* qrow = (const float4*)&Qsh[tid * QPAD];
#pragma unroll
        for (int i = 0; i < 16; i++) qr[i] = qrow[i];

        float* prow = &Psh[tid * Tt];
        for (int t = 0; t < Tt; t++) {
            const float4* kp = (const float4*)&Ksh[t * HDd];
            float a0 = 0.f, a1 = 0.f, a2 = 0.f, a3 = 0.f;
#pragma unroll
            for (int i = 0; i < 16; i++) {
                const float4 kv = kp[i];
                a0 = fmaf(qr[i].x, kv.x, a0);
                a1 = fmaf(qr[i].y, kv.y, a1);
                a2 = fmaf(qr[i].z, kv.z, a2);
                a3 = fmaf(qr[i].w, kv.w, a3);
            }
            prow[t] = ((a0 + a1) + (a2 + a3)) * 0.125f;
        }
    }

    float* prow = &Psh[tid * Tt];

    float e0s[8], e1s[8];
#pragma unroll
    for (int j = 0; j < 8; j++) { e0s[j] = prow[si0[j]]; e1s[j] = prow[si1[j]]; }

    float m = -1e30f;
    for (int t = 0; t < Tt; t++) m = fmaxf(m, prow[t]);
    float z = 0.f;
    for (int t = 0; t < Tt; t++) { const float p = expf(prow[t] - m); prow[t] = p; z += p; }
    const float invz = 1.f / z;

    float m0 = -1e30f, m1 = -1e30f;
#pragma unroll
    for (int j = 0; j < 8; j++) { m0 = fmaxf(m0, e0s[j]); m1 = fmaxf(m1, e1s[j]); }
    float z0 = 0.f, z1 = 0.f;
#pragma unroll
    for (int j = 0; j < 8; j++) {
        e0s[j] = expf(e0s[j] - m0); z0 += e0s[j];
        e1s[j] = expf(e1s[j] - m1); z1 += e1s[j];
    }
    const float invz0 = c1 / z0, invz1 = c1 / z1;
    const float rz0 = 1.f / z0, rz1 = 1.f / z1;

    const int s = s0 + tid;
    const size_t fbase = (size_t)(b * Ss + s) * Dd + h * HDd;
    const size_t gbase = (size_t)(b * Ss + s) * KB + h * HDd;

    float4 Gacc[16];
#pragma unroll
    for (int i = 0; i < 16; i++) Gacc[i] = make_float4(0.f, 0.f, 0.f, 0.f);

    // entity 0
    {
        float4 acc[16];
#pragma unroll
        for (int i = 0; i < 16; i++) acc[i] = make_float4(0.f, 0.f, 0.f, 0.f);
#pragma unroll
        for (int j = 0; j < 8; j++) {
            const float p = e0s[j];
            const float4* vp = (const float4*)&Vsh[si0[j] * HDd];
#pragma unroll
            for (int i = 0; i < 16; i++) {
                const float4 vv = vp[i];
                acc[i].x = fmaf(p, vv.x, acc[i].x);
                acc[i].y = fmaf(p, vv.y, acc[i].y);
                acc[i].z = fmaf(p, vv.z, acc[i].z);
                acc[i].w = fmaf(p, vv.w, acc[i].w);
            }
        }
        float4* og = (float4*)(F0 + fbase);
#pragma unroll
        for (int i = 0; i < 16; i++) {
            og[i] = make_float4(acc[i].x * rz0, acc[i].y * rz0, acc[i].z * rz0, acc[i].w * rz0);
            Gacc[i].x = fmaf(acc[i].x, invz0, Gacc[i].x);
            Gacc[i].y = fmaf(acc[i].y, invz0, Gacc[i].y);
            Gacc[i].z = fmaf(acc[i].z, invz0, Gacc[i].z);
            Gacc[i].w = fmaf(acc[i].w, invz0, Gacc[i].w);
        }
    }
    // entity 1
    {
        float4 acc[16];
#pragma unroll
        for (int i = 0; i < 16; i++) acc[i] = make_float4(0.f, 0.f, 0.f, 0.f);
#pragma unroll
        for (int j = 0; j < 8; j++) {
            const float p = e1s[j];
            const float4* vp = (const float4*)&Vsh[si1[j] * HDd];
#pragma unroll
            for (int i = 0; i < 16; i++) {
                const float4 vv = vp[i];
                acc[i].x = fmaf(p, vv.x, acc[i].x);
                acc[i].y = fmaf(p, vv.y, acc[i].y);
                acc[i].z = fmaf(p, vv.z, acc[i].z);
                acc[i].w = fmaf(p, vv.w, acc[i].w);
            }
        }
        float4* og = (float4*)(F1 + fbase);
#pragma unroll
        for (int i = 0; i < 16; i++) {
            og[i] = make_float4(acc[i].x * rz1, acc[i].y * rz1, acc[i].z * rz1, acc[i].w * rz1);
            Gacc[i].x = fmaf(acc[i].x, invz1, Gacc[i].x);
            Gacc[i].y = fmaf(acc[i].y, invz1, Gacc[i].y);
            Gacc[i].z = fmaf(acc[i].z, invz1, Gacc[i].z);
            Gacc[i].w = fmaf(acc[i].w, invz1, Gacc[i].w);
        }
    }
    // global
    {
        float4 acc[16];
#pragma unroll
        for (int i = 0; i < 16; i++) acc[i] = make_float4(0.f, 0.f, 0.f, 0.f);
        for (int t = 0; t < Tt; t++) {
            const float p = prow[t];
            const float4* vp = (const float4*)&Vsh[t * HDd];
#pragma unroll
            for (int i = 0; i < 16; i++) {
                const float4 vv = vp[i];
                acc[i].x = fmaf(p, vv.x, acc[i].x);
                acc[i].y = fmaf(p, vv.y, acc[i].y);
                acc[i].z = fmaf(p, vv.z, acc[i].z);
                acc[i].w = fmaf(p, vv.w, acc[i].w);
            }
        }
        const float cz = c2 * invz;
        float4* og = (float4*)(Abig + gbase);
#pragma unroll
        for (int i = 0; i < 16; i++) {
            og[i] = make_float4(fmaf(acc[i].x, cz, Gacc[i].x),
                                fmaf(acc[i].y, cz, Gacc[i].y),
                                fmaf(acc[i].z, cz, Gacc[i].z),
                                fmaf(acc[i].w, cz, Gacc[i].w));
        }
    }
}

// ---------------- fused adapters: LN -> down-proj -> SiLU -> h into Abig --------
constexpr int NR = 16;
constexpr int ADP_SMEM_FLOATS = 2 * NR * Dd + 2 * NR * Rr;

__global__ __launch_bounds__(256)
void adapter_kernel(const float* __restrict__ F0, const float* __restrict__ F1,
                    const float* __restrict__ ln0g, const float* __restrict__ ln0b,
                    const float* __restrict__ d0W,  const float* __restrict__ d0b,
                    const float* __restrict__ ln1g, const float* __restrict__ ln1b,
                    const float* __restrict__ d1W,  const float* __restrict__ d1b,
                    float* __restrict__ Abig)
{
    extern __shared__ float sm[];
    float* n0 = sm;
    float* n1 = n0 + NR * Dd;
    float* hsm = n1 + NR * Dd;    // [2][Rr][NR]

    const int tid = threadIdx.x;
    const int wid = tid >> 5;
    const int lane = tid & 31;
    const int row0 = blockIdx.x * NR;

    for (int task = wid; task < 2 * NR; task += 8) {
        const int a = task / NR;
        const int r = task % NR;
        const float* src = (a ? F1 : F0) + (size_t)(row0 + r) * Dd;
        float vals[20];
        float sum = 0.f;
#pragma unroll
        for (int i = 0; i < 20; i++) { vals[i] = src[lane + 32 * i]; sum += vals[i]; }
#pragma unroll
        for (int o = 16; o > 0; o >>= 1) sum += __shfl_xor_sync(0xffffffffu, sum, o);
        const float mean = sum * (1.f / Dd);
        float vs = 0.f;
#pragma unroll
        for (int i = 0; i < 20; i++) { const float dv = vals[i] - mean; vs = fmaf(dv, dv, vs); }
#pragma unroll
        for (int o = 16; o > 0; o >>= 1) vs += __shfl_xor_sync(0xffffffffu, vs, o);
        const float rstd = rsqrtf(vs * (1.f / Dd) + LN_EPS);
        const float* gg = a ? ln1g : ln0g;
        const float* be = a ? ln1b : ln0b;
        float* dst = (a ? n1 : n0) + r * Dd;
#pragma unroll
        for (int i = 0; i < 20; i++) {
            const int d = lane + 32 * i;
            dst[d] = (vals[i] - mean) * rstd * gg[d] + be[d];
        }
    }
    __syncthreads();

    for (int task = wid; task < 2 * Rr; task += 8) {
        const int a = task / Rr;
        const int r = task % Rr;
        const float* W = (a ? d1W : d0W) + (size_t)r * Dd;
        const float* nn = a ? n1 : n0;
        float acc[NR];
#pragma unroll
        for (int rw = 0; rw < NR; rw++) acc[rw] = 0.f;
        for (int i = 0; i < 20; i++) {
            const float w = W[lane + 32 * i];
#pragma unroll
            for (int rw = 0; rw < NR; rw++)
                acc[rw] = fmaf(w, nn[rw * Dd + lane + 32 * i], acc[rw]);
        }
#pragma unroll
        for (int rw = 0; rw < NR; rw++) {
#pragma unroll
            for (int o = 16; o > 0; o >>= 1)
                acc[rw] += __shfl_xor_sync(0xffffffffu, acc[rw], o);
        }
        if (lane == 0) {
            const float db = (a ? d1b : d0b)[r];
            float* hdst = hsm + a * (Rr * NR) + r * NR;
#pragma unroll
            for (int rw = 0; rw < NR; rw++) {
                const float x = acc[rw] + db;
                hdst[rw] = x / (1.f + expf(-x));
            }
        }
    }
    __syncthreads();

    for (int idx = tid; idx < 2 * Rr * NR; idx += 256) {
        const int rw = idx >> 7;
        const int c  = idx & 127;
        const int a  = c >> 6;
        const int r  = c & 63;
        Abig[(size_t)(row0 + rw) * KB + Dd + c] = hsm[a * (Rr * NR) + r * NR + rw];
    }
}

// ---------------- launch ----------------
extern "C" void kernel_launch(void* const* d_in, const int* in_sizes, int n_in,
                              void* d_out, int out_size)
{
    (void)in_sizes; (void)n_in; (void)out_size;
    const float* hs   = (const float*)d_in[0];
    const float* enc  = (const float*)d_in[1];
    const float* Wq   = (const float*)d_in[2];
    const float* Wk   = (const float*)d_in[3];
    const float* Wv   = (const float*)d_in[4];
    const float* Wo   = (const float*)d_in[5];
    const float* bo   = (const float*)d_in[6];
    const float* ln0g = (const float*)d_in[7];
    const float* ln0b = (const float*)d_in[8];
    const float* d0W  = (const float*)d_in[9];
    const float* d0b  = (const float*)d_in[10];
    const float* u0W  = (const float*)d_in[11];
    const float* u0b  = (const float*)d_in[12];
    const float* ln1g = (const float*)d_in[13];
    const float* ln1b = (const float*)d_in[14];
    const float* d1W  = (const float*)d_in[15];
    const float* d1b  = (const float*)d_in[16];
    const float* u1W  = (const float*)d_in[17];
    const float* u1b  = (const float*)d_in[18];
    const float* sbr  = (const float*)d_in[19];
    const int*   idx0 = (const int*)d_in[20];
    const int*   idx1 = (const int*)d_in[21];
    float* out = (float*)d_out;

    float *pq, *pk, *pv, *pF0, *pF1, *pA, *pW, *pb2;
    cudaGetSymbolAddress((void**)&pq,  g_q);
    cudaGetSymbolAddress((void**)&pk,  g_k);
    cudaGetSymbolAddress((void**)&pv,  g_v);
    cudaGetSymbolAddress((void**)&pF0, g_F0);
    cudaGetSymbolAddress((void**)&pF1, g_F1);
    cudaGetSymbolAddress((void**)&pA,  g_Abig);
    cudaGetSymbolAddress((void**)&pW,  g_Wbig);
    cudaGetSymbolAddress((void**)&pb2, g_bo2);

    const int att_smem = ATT_SMEM_FLOATS * (int)sizeof(float);
    const int adp_smem = ADP_SMEM_FLOATS * (int)sizeof(float);
    cudaFuncSetAttribute(attn_kernel, cudaFuncAttributeMaxDynamicSharedMemorySize, att_smem);
    cudaFuncSetAttribute(adapter_kernel, cudaFuncAttributeMaxDynamicSharedMemorySize, adp_smem);
    cudaFuncSetAttribute((const void*)gemm_tf32_kernel<false, true>,  cudaFuncAttributeMaxDynamicSharedMemorySize, GEMM_SMEM_BYTES);
    cudaFuncSetAttribute((const void*)gemm_tf32_kernel<false, false>, cudaFuncAttributeMaxDynamicSharedMemorySize, GEMM_SMEM_BYTES);
    cudaFuncSetAttribute((const void*)gemm_tf32_kernel<true, true>,   cudaFuncAttributeMaxDynamicSharedMemorySize, GEMM_SMEM_BYTES);

    const int MKV = Bn * Tt;          // 616
    const int MQ  = Bn * Ss;          // 32768

    // 1) prep (independent — placed first so launch #4 is the Q GEMM for ncu)
    prep_kernel<<<Dd / PREP_E, 256>>>(Wo, u0W, u1W, u0b, u1b, bo, sbr, pW, pb2);

    // 2,3) K/V projections (M=616, not full)
    {
        dim3 grid(Dd / 128, (MKV + 127) / 128);
        gemm_tf32_kernel<false, false><<<grid, 256, GEMM_SMEM_BYTES>>>(enc, Wk, nullptr, pk, MKV, Dd, DEe);
        gemm_tf32_kernel<false, false><<<grid, 256, GEMM_SMEM_BYTES>>>(enc, Wv, nullptr, pv, MKV, Dd, DEe);
    }
    // 4) Q projection (full tiles)
    {
        dim3 grid(Dd / 128, MQ / 128);
        gemm_tf32_kernel<false, true><<<grid, 256, GEMM_SMEM_BYTES>>>(hs, Wq, nullptr, pq, MQ, Dd, Dd);
    }
    // 5) fused attention
    {
        dim3 grid(Ss / ATT_QT, Bn * Hh);
        attn_kernel<<<grid, ATT_QT, att_smem>>>(pq, pk, pv, idx0, idx1, sbr, pF0, pF1, pA);
    }
    // 6) adapters
    adapter_kernel<<<MQ / NR, 256, adp_smem>>>(pF0, pF1,
                                               ln0g, ln0b, d0W, d0b,
                                               ln1g, ln1b, d1W, d1b, pA);
    // 7) fused output GEMM (full tiles)
    {
        dim3 grid(Dd / 128, MQ / 128);
        gemm_tf32_kernel<true, true><<<grid, 256, GEMM_SMEM_BYTES>>>(pA, pW, pb2, out, MQ, Dd, KB);
    }
}

// round 6
// speedup vs baseline: 1.6056x; 1.6056x over previous
#include <cuda_runtime.h>
#include <cstdint>

// Problem constants
constexpr int Bn  = 8;
constexpr int Ss  = 4096;
constexpr int Dd  = 640;
constexpr int Tt  = 77;
constexpr int DEe = 768;
constexpr int Hh  = 10;
constexpr int HDd = 64;
constexpr int Rr  = 64;
constexpr int KB  = 768;   // fused final-GEMM K = Dd + 2*Rr
constexpr float LN_EPS = 1e-5f;

// ---------------- scratch (static device globals; no allocation) ----------------
__device__ float g_q   [(size_t)Bn*Ss*Dd];   // Q proj; reused as n0 after attention
__device__ float g_n1  [(size_t)Bn*Ss*Dd];
__device__ float g_k   [(size_t)Bn*Tt*Dd];
__device__ float g_v   [(size_t)Bn*Tt*Dd];
__device__ float g_F0  [(size_t)Bn*Ss*Dd];
__device__ float g_F1  [(size_t)Bn*Ss*Dd];
__device__ float g_Abig[(size_t)Bn*Ss*KB];   // [G | h0 | h1]  (tf32-rounded)
__device__ float g_Wbig[(size_t)Dd*KB];      // [Wo | c1*M0 | c1*M1] (tf32-rounded)
__device__ float g_bo2 [Dd];
// tf32-pre-rounded GEMM inputs
__device__ float g_hsr [(size_t)Bn*Ss*Dd];
__device__ float g_encr[(size_t)Bn*Tt*DEe];
__device__ float g_wqr [(size_t)Dd*Dd];
__device__ float g_wkr [(size_t)Dd*DEe];
__device__ float g_wvr [(size_t)Dd*DEe];
__device__ float g_dw0r[(size_t)Rr*Dd];
__device__ float g_dw1r[(size_t)Rr*Dd];

__device__ __forceinline__ uint32_t f2tf32(float x) {
    uint32_t r;
    asm("cvt.rna.tf32.f32 %0, %1;" : "=r"(r) : "f"(x));
    return r;
}
__device__ __forceinline__ float roundtf(float x) { return __uint_as_float(f2tf32(x)); }

__device__ __forceinline__ void mma_tf32(float c[4], const uint32_t a[4], const uint32_t b[2]) {
    asm volatile(
        "mma.sync.aligned.m16n8k8.row.col.f32.tf32.tf32.f32 "
        "{%0,%1,%2,%3}, {%4,%5,%6,%7}, {%8,%9}, {%0,%1,%2,%3};"
        : "+f"(c[0]), "+f"(c[1]), "+f"(c[2]), "+f"(c[3])
        : "r"(a[0]), "r"(a[1]), "r"(a[2]), "r"(a[3]), "r"(b[0]), "r"(b[1]));
}

__device__ __forceinline__ void cp_async16(uint32_t dst, const void* src, bool pred) {
    const int nbytes = pred ? 16 : 0;
    asm volatile("cp.async.cg.shared.global [%0], [%1], 16, %2;"
                 :: "r"(dst), "l"(src), "r"(nbytes));
}
__device__ __forceinline__ void cp_commit() { asm volatile("cp.async.commit_group;"); }
__device__ __forceinline__ void cp_wait0()  { asm volatile("cp.async.wait_group 0;"); }

// ---------------- round inputs to tf32 (rna) once ----------------
__global__ void round_kernel(const float* __restrict__ hs,  float* __restrict__ hsr,
                             const float* __restrict__ enc, float* __restrict__ encr,
                             const float* __restrict__ Wq,  float* __restrict__ wqr,
                             const float* __restrict__ Wk,  float* __restrict__ wkr,
                             const float* __restrict__ Wv,  float* __restrict__ wvr,
                             const float* __restrict__ d0W, float* __restrict__ dw0r,
                             const float* __restrict__ d1W, float* __restrict__ dw1r)
{
    const long n_hs  = (long)Bn*Ss*Dd;
    const long n_enc = (long)Bn*Tt*DEe;
    const long n_wq  = (long)Dd*Dd;
    const long n_wk  = (long)Dd*DEe;
    const long n_dw  = (long)Rr*Dd;
    const long tot4 = (n_hs + n_enc + n_wq + 2*n_wk + 2*n_dw) / 4;
    for (long i4 = blockIdx.x * (long)blockDim.x + threadIdx.x; i4 < tot4;
         i4 += (long)gridDim.x * blockDim.x) {
        long i = i4 * 4;
        const float* s; float* d;
        if      (i < n_hs)                         { s = hs  + i;                     d = hsr  + i; }
        else if (i < n_hs+n_enc)                   { s = enc + (i-n_hs);              d = encr + (i-n_hs); }
        else if (i < n_hs+n_enc+n_wq)              { s = Wq  + (i-n_hs-n_enc);        d = wqr  + (i-n_hs-n_enc); }
        else if (i < n_hs+n_enc+n_wq+n_wk)         { s = Wk  + (i-n_hs-n_enc-n_wq);   d = wkr  + (i-n_hs-n_enc-n_wq); }
        else if (i < n_hs+n_enc+n_wq+2*n_wk)       { s = Wv  + (i-n_hs-n_enc-n_wq-n_wk); d = wvr + (i-n_hs-n_enc-n_wq-n_wk); }
        else if (i < n_hs+n_enc+n_wq+2*n_wk+n_dw)  { s = d0W + (i-n_hs-n_enc-n_wq-2*n_wk); d = dw0r + (i-n_hs-n_enc-n_wq-2*n_wk); }
        else                                       { s = d1W + (i-n_hs-n_enc-n_wq-2*n_wk-n_dw); d = dw1r + (i-n_hs-n_enc-n_wq-2*n_wk-n_dw); }
        float4 v = *(const float4*)s;
        v.x = roundtf(v.x); v.y = roundtf(v.y); v.z = roundtf(v.z); v.w = roundtf(v.w);
        *(float4*)d = v;
    }
}

// ================= TF32 GEMM: C[m,n] = sum_k A[m,k]*W[n,k] (+epilogue) ==========
// Inputs already tf32-rounded in global. cp.async 2-stage ping-pong, no cvt.
// 128x128 tile, BK=32, 8 warps x (64x32), mma.m16n8k8.
constexpr int GLDA = 36;
constexpr int GEMM_STAGE = 128 * GLDA;                   // u32 per matrix per stage
constexpr int GEMM_SMEM_BYTES = 2 * 2 * GEMM_STAGE * 4;  // 73728

// EPI: 0 = none, 1 = +bias, 2 = silu(acc+bias) rounded to tf32
template<int EPI, bool FULL>
__global__ __launch_bounds__(256, 2)
void gemm_tf32_kernel(const float* __restrict__ A, const float* __restrict__ W,
                      const float* __restrict__ bias, float* __restrict__ C,
                      int M, int N, int K, int ldc)
{
    extern __shared__ uint32_t smem_u[];
    uint32_t* AsBase = smem_u;
    uint32_t* BsBase = smem_u + GEMM_STAGE;
    const uint32_t smem_addr = (uint32_t)__cvta_generic_to_shared(smem_u);

    const int tid  = threadIdx.x;
    const int wid  = tid >> 5;
    const int lane = tid & 31;
    const int g    = lane >> 2;
    const int tg   = lane & 3;

    const int m0 = blockIdx.y * 128;
    const int n0 = blockIdx.x * 128;
    const int wm = (wid & 1) * 64;
    const int wn = (wid >> 1) * 32;

    const int ldrow = tid >> 3;        // 0..31
    const int ldseg = tid & 7;         // float4 segment

    float acc[4][4][4];
#pragma unroll
    for (int i = 0; i < 4; i++)
#pragma unroll
        for (int j = 0; j < 4; j++)
#pragma unroll
            for (int r = 0; r < 4; r++) acc[i][j][r] = 0.f;

    auto stage_cp = [&](int k0, int stage) {
        const uint32_t abase = smem_addr + stage * (2 * GEMM_STAGE * 4);
        const uint32_t bbase = abase + GEMM_STAGE * 4;
#pragma unroll
        for (int p = 0; p < 4; p++) {
            const int row = ldrow + p * 32;
            const int gm = m0 + row;
            const int gn = n0 + row;
            const uint32_t soff = (row * GLDA + ldseg * 4) * 4;
            if (FULL) {
                cp_async16(abase + soff, A + (size_t)gm * K + k0 + ldseg * 4, true);
                cp_async16(bbase + soff, W + (size_t)gn * K + k0 + ldseg * 4, true);
            } else {
                const int gmc = gm < M ? gm : M - 1;
                const int gnc = gn < N ? gn : N - 1;
                cp_async16(abase + soff, A + (size_t)gmc * K + k0 + ldseg * 4, gm < M);
                cp_async16(bbase + soff, W + (size_t)gnc * K + k0 + ldseg * 4, gn < N);
            }
        }
        cp_commit();
    };

    stage_cp(0, 0);

    int cur = 0;
    for (int k0 = 0; k0 < K; k0 += 32) {
        cp_wait0();        // copies for 'cur' landed (this thread)
        __syncthreads();   // all threads; also: everyone done reading cur^1

        if (k0 + 32 < K) stage_cp(k0 + 32, cur ^ 1);

        const uint32_t* As = AsBase + cur * (2 * GEMM_STAGE);
        const uint32_t* Bs = BsBase + cur * (2 * GEMM_STAGE);
#pragma unroll
        for (int ka = 0; ka < 4; ka++) {
            const int kc = ka * 8;
            uint32_t afr[4][4];
            uint32_t bfr[4][2];
#pragma unroll
            for (int i = 0; i < 4; i++) {
                const int r0 = wm + 16 * i + g;
                afr[i][0] = As[r0 * GLDA + kc + tg];
                afr[i][1] = As[(r0 + 8) * GLDA + kc + tg];
                afr[i][2] = As[r0 * GLDA + kc + tg + 4];
                afr[i][3] = As[(r0 + 8) * GLDA + kc + tg + 4];
            }
#pragma unroll
            for (int j = 0; j < 4; j++) {
                const int nrow = wn + 8 * j + g;
                bfr[j][0] = Bs[nrow * GLDA + kc + tg];
                bfr[j][1] = Bs[nrow * GLDA + kc + tg + 4];
            }
#pragma unroll
            for (int i = 0; i < 4; i++)
#pragma unroll
                for (int j = 0; j < 4; j++)
                    mma_tf32(acc[i][j], afr[i], bfr[j]);
        }
        cur ^= 1;
    }

#pragma unroll
    for (int i = 0; i < 4; i++) {
        const int rowA = m0 + wm + 16 * i + g;
        const int rowB = rowA + 8;
#pragma unroll
        for (int j = 0; j < 4; j++) {
            const int col = n0 + wn + 8 * j + 2 * tg;
            if (!FULL && col >= N) continue;
            float2 bv = make_float2(0.f, 0.f);
            if (EPI >= 1) bv = *(const float2*)(bias + col);
#pragma unroll
            for (int h = 0; h < 2; h++) {
                const int row = h ? rowB : rowA;
                if (!FULL && row >= M) continue;
                float x = acc[i][j][2 * h]     + bv.x;
                float y = acc[i][j][2 * h + 1] + bv.y;
                if (EPI == 2) {
                    x = roundtf(x / (1.f + expf(-x)));
                    y = roundtf(y / (1.f + expf(-y)));
                }
                *(float2*)(C + (size_t)row * ldc + col) = make_float2(x, y);
            }
        }
    }
}

// ---------------- prep: fold up-proj weights through Wo (exact fp32) ------------
constexpr int PREP_E = 8;
constexpr int PREP_DC = 64;

__global__ __launch_bounds__(256)
void prep_kernel(const float* __restrict__ Wo,
                 const float* __restrict__ u0W, const float* __restrict__ u1W,
                 const float* __restrict__ u0b, const float* __restrict__ u1b,
                 const float* __restrict__ bo,  const float* __restrict__ sbr,
                 float* __restrict__ Wbig, float* __restrict__ bo2)
{
    __shared__ float sWo[PREP_E][PREP_DC];
    __shared__ float su0[PREP_DC][Rr];
    __shared__ float su1[PREP_DC][Rr];

    const int tid = threadIdx.x;
    const int e0  = blockIdx.x * PREP_E;
    const int el  = tid >> 5;
    const int rl  = tid & 31;
    const float blend = 1.f / (1.f + expf(-*sbr));
    const float c1 = blend * (1.f / 3.f);

    float a00 = 0.f, a01 = 0.f, a10 = 0.f, a11 = 0.f;

    for (int d0 = 0; d0 < Dd; d0 += PREP_DC) {
        for (int i = tid; i < PREP_E * PREP_DC; i += 256) {
            const int e = i >> 6, d = i & 63;
            sWo[e][d] = Wo[(size_t)(e0 + e) * Dd + d0 + d];
        }
        for (int i = tid; i < PREP_DC * Rr; i += 256) {
            const int d = i >> 6, r = i & 63;
            su0[d][r] = u0W[(size_t)(d0 + d) * Rr + r];
            su1[d][r] = u1W[(size_t)(d0 + d) * Rr + r];
        }
        __syncthreads();
#pragma unroll 8
        for (int dd = 0; dd < PREP_DC; dd++) {
            const float w = sWo[el][dd];
            a00 = fmaf(w, su0[dd][rl],      a00);
            a01 = fmaf(w, su0[dd][rl + 32], a01);
            a10 = fmaf(w, su1[dd][rl],      a10);
            a11 = fmaf(w, su1[dd][rl + 32], a11);
        }
        __syncthreads();
    }

    const int e = e0 + el;
    {
        float* dst = Wbig + (size_t)e * KB;
        dst[Dd + rl]           = roundtf(c1 * a00);
        dst[Dd + rl + 32]      = roundtf(c1 * a01);
        dst[Dd + Rr + rl]      = roundtf(c1 * a10);
        dst[Dd + Rr + rl + 32] = roundtf(c1 * a11);
    }
    // copy Wo rows (rounded) into Wbig cols [0,640)
    for (int i = tid; i < PREP_E * (Dd / 4); i += 256) {
        const int er = i / (Dd / 4);
        const int d4 = i % (Dd / 4);
        float4 v = *(const float4*)(Wo + (size_t)(e0 + er) * Dd + d4 * 4);
        v.x = roundtf(v.x); v.y = roundtf(v.y); v.z = roundtf(v.z); v.w = roundtf(v.w);
        *(float4*)(Wbig + (size_t)(e0 + er) * KB + d4 * 4) = v;
    }
    // bias (exact fp32)
    {
        float s = 0.f;
        for (int d = rl; d < Dd; d += 32)
            s = fmaf(Wo[(size_t)e * Dd + d], u0b[d] + u1b[d], s);
#pragma unroll
        for (int o = 16; o > 0; o >>= 1) s += __shfl_xor_sync(0xffffffffu, s, o);
        if (rl == 0) bo2[e] = bo[e] + c1 * s;
    }
}

// ---------------- fused attention (no Qsh; 2 blocks/SM) ------------------------
constexpr int ATT_QT = 128;
constexpr int ATT_SMEM_FLOATS = 2 * Tt * HDd + ATT_QT * Tt;   // 19712 = 78.8 KB

__global__ __launch_bounds__(128, 2)
void attn_kernel(const float* __restrict__ q, const float* __restrict__ k,
                 const float* __restrict__ v,
                 const int* __restrict__ idx0, const int* __restrict__ idx1,
                 const float* __restrict__ sbr,
                 float* __restrict__ F0, float* __restrict__ F1,
                 float* __restrict__ Abig)
{
    extern __shared__ float sm[];
    float* Ksh = sm;                       // Tt*HDd
    float* Vsh = Ksh + Tt * HDd;           // Tt*HDd
    float* Psh = Vsh + Tt * HDd;           // ATT_QT*Tt
    __shared__ int si0[8], si1[8];

    const int tid = threadIdx.x;
    const int b = blockIdx.y / Hh;
    const int h = blockIdx.y % Hh;
    const int s0 = blockIdx.x * ATT_QT;

    if (tid < 8) { si0[tid] = idx0[tid]; si1[tid] = idx1[tid]; }

    const float blend = 1.f / (1.f + expf(-*sbr));
    const float c1 = blend * (1.f / 3.f);
    const float c2 = 1.f - 2.f * blend * (1.f / 3.f);

    const float* kb = k + (size_t)b * Tt * Dd + h * HDd;
    const float* vb = v + (size_t)b * Tt * Dd + h * HDd;
    for (int i = tid; i < Tt * HDd; i += ATT_QT) {
        const int t = i >> 6, d = i & 63;
        Ksh[i] = kb[(size_t)t * Dd + d];
        Vsh[i] = vb[(size_t)t * Dd + d];
    }
    __syncthreads();

    const int s = s0 + tid;
    // q row straight from global into registers
    float4 qr[16];
    {
        const float4* qrow = (const float4*)(q + (size_t)(b * Ss + s) * Dd + h * HDd);
#pragma unroll
        for (int i = 0; i < 16; i++) qr[i] = qrow[i];
    }

    float* prow = &Psh[tid * Tt];
    for (int t = 0; t < Tt; t++) {
        const float4* kp = (const float4*)&Ksh[t * HDd];
        float a0 = 0.f, a1 = 0.f, a2 = 0.f, a3 = 0.f;
#pragma unroll
        for (int i = 0; i < 16; i++) {
            const float4 kv = kp[i];
            a0 = fmaf(qr[i].x, kv.x, a0);
            a1 = fmaf(qr[i].y, kv.y, a1);
            a2 = fmaf(qr[i].z, kv.z, a2);
            a3 = fmaf(qr[i].w, kv.w, a3);
        }
        prow[t] = ((a0 + a1) + (a2 + a3)) * 0.125f;
    }

    float e0s[8], e1s[8];
#pragma unroll
    for (int j = 0; j < 8; j++) { e0s[j] = prow[si0[j]]; e1s[j] = prow[si1[j]]; }

    float m = -1e30f;
    for (int t = 0; t < Tt; t++) m = fmaxf(m, prow[t]);
    float z = 0.f;
    for (int t = 0; t < Tt; t++) { const float p = expf(prow[t] - m); prow[t] = p; z += p; }
    const float invz = 1.f / z;

    float m0 = -1e30f, m1 = -1e30f;
#pragma unroll
    for (int j = 0; j < 8; j++) { m0 = fmaxf(m0, e0s[j]); m1 = fmaxf(m1, e1s[j]); }
    float z0 = 0.f, z1 = 0.f;
#pragma unroll
    for (int j = 0; j < 8; j++) {
        e0s[j] = expf(e0s[j] - m0); z0 += e0s[j];
        e1s[j] = expf(e1s[j] - m1); z1 += e1s[j];
    }
    const float invz0 = c1 / z0, invz1 = c1 / z1;
    const float rz0 = 1.f / z0, rz1 = 1.f / z1;

    const size_t fbase = (size_t)(b * Ss + s) * Dd + h * HDd;
    const size_t gbase = (size_t)(b * Ss + s) * KB + h * HDd;

    float4 Gacc[16];
#pragma unroll
    for (int i = 0; i < 16; i++) Gacc[i] = make_float4(0.f, 0.f, 0.f, 0.f);

    // entity 0
    {
        float4 acc[16];
#pragma unroll
        for (int i = 0; i < 16; i++) acc[i] = make_float4(0.f, 0.f, 0.f, 0.f);
#pragma unroll
        for (int j = 0; j < 8; j++) {
            const float p = e0s[j];
            const float4* vp = (const float4*)&Vsh[si0[j] * HDd];
#pragma unroll
            for (int i = 0; i < 16; i++) {
                const float4 vv = vp[i];
                acc[i].x = fmaf(p, vv.x, acc[i].x);
                acc[i].y = fmaf(p, vv.y, acc[i].y);
                acc[i].z = fmaf(p, vv.z, acc[i].z);
                acc[i].w = fmaf(p, vv.w, acc[i].w);
            }
        }
        float4* og = (float4*)(F0 + fbase);
#pragma unroll
        for (int i = 0; i < 16; i++) {
            og[i] = make_float4(acc[i].x * rz0, acc[i].y * rz0, acc[i].z * rz0, acc[i].w * rz0);
            Gacc[i].x = fmaf(acc[i].x, invz0, Gacc[i].x);
            Gacc[i].y = fmaf(acc[i].y, invz0, Gacc[i].y);
            Gacc[i].z = fmaf(acc[i].z, invz0, Gacc[i].z);
            Gacc[i].w = fmaf(acc[i].w, invz0, Gacc[i].w);
        }
    }
    // entity 1
    {
        float4 acc[16];
#pragma unroll
        for (int i = 0; i < 16; i++) acc[i] = make_float4(0.f, 0.f, 0.f, 0.f);
#pragma unroll
        for (int j = 0; j < 8; j++) {
            const float p = e1s[j];
            const float4* vp = (const float4*)&Vsh[si1[j] * HDd];
#pragma unroll
            for (int i = 0; i < 16; i++) {
                const float4 vv = vp[i];
                acc[i].x = fmaf(p, vv.x, acc[i].x);
                acc[i].y = fmaf(p, vv.y, acc[i].y);
                acc[i].z = fmaf(p, vv.z, acc[i].z);
                acc[i].w = fmaf(p, vv.w, acc[i].w);
            }
        }
        float4* og = (float4*)(F1 + fbase);
#pragma unroll
        for (int i = 0; i < 16; i++) {
            og[i] = make_float4(acc[i].x * rz1, acc[i].y * rz1, acc[i].z * rz1, acc[i].w * rz1);
            Gacc[i].x = fmaf(acc[i].x, invz1, Gacc[i].x);
            Gacc[i].y = fmaf(acc[i].y, invz1, Gacc[i].y);
            Gacc[i].z = fmaf(acc[i].z, invz1, Gacc[i].z);
            Gacc[i].w = fmaf(acc[i].w, invz1, Gacc[i].w);
        }
    }
    // global + write rounded G
    {
        float4 acc[16];
#pragma unroll
        for (int i = 0; i < 16; i++) acc[i] = make_float4(0.f, 0.f, 0.f, 0.f);
        for (int t = 0; t < Tt; t++) {
            const float p = prow[t];
            const float4* vp = (const float4*)&Vsh[t * HDd];
#pragma unroll
            for (int i = 0; i < 16; i++) {
                const float4 vv = vp[i];
                acc[i].x = fmaf(p, vv.x, acc[i].x);
                acc[i].y = fmaf(p, vv.y, acc[i].y);
                acc[i].z = fmaf(p, vv.z, acc[i].z);
                acc[i].w = fmaf(p, vv.w, acc[i].w);
            }
        }
        const float cz = c2 * invz;
        float4* og = (float4*)(Abig + gbase);
#pragma unroll
        for (int i = 0; i < 16; i++) {
            og[i] = make_float4(roundtf(fmaf(acc[i].x, cz, Gacc[i].x)),
                                roundtf(fmaf(acc[i].y, cz, Gacc[i].y)),
                                roundtf(fmaf(acc[i].z, cz, Gacc[i].z)),
                                roundtf(fmaf(acc[i].w, cz, Gacc[i].w)));
        }
    }
}

// ---------------- LayerNorm only: F0/F1 -> rounded n0/n1 -----------------------
__global__ __launch_bounds__(256)
void ln_kernel(const float* __restrict__ F0, const float* __restrict__ F1,
               const float* __restrict__ ln0g, const float* __restrict__ ln0b,
               const float* __restrict__ ln1g, const float* __restrict__ ln1b,
               float* __restrict__ n0, float* __restrict__ n1)
{
    const int wid  = threadIdx.x >> 5;
    const int lane = threadIdx.x & 31;
    const int task = blockIdx.x * 8 + wid;           // 0 .. 2*B*S-1
    const int a    = task >= Bn * Ss;
    const int row  = a ? task - Bn * Ss : task;

    const float* src = (a ? F1 : F0) + (size_t)row * Dd;
    float vals[20];
    float sum = 0.f;
#pragma unroll
    for (int i = 0; i < 20; i++) { vals[i] = src[lane + 32 * i]; sum += vals[i]; }
#pragma unroll
    for (int o = 16; o > 0; o >>= 1) sum += __shfl_xor_sync(0xffffffffu, sum, o);
    const float mean = sum * (1.f / Dd);
    float vs = 0.f;
#pragma unroll
    for (int i = 0; i < 20; i++) { const float dv = vals[i] - mean; vs = fmaf(dv, dv, vs); }
#pragma unroll
    for (int o = 16; o > 0; o >>= 1) vs += __shfl_xor_sync(0xffffffffu, vs, o);
    const float rstd = rsqrtf(vs * (1.f / Dd) + LN_EPS);
    const float* gg = a ? ln1g : ln0g;
    const float* be = a ? ln1b : ln0b;
    float* dst = (a ? n1 : n0) + (size_t)row * Dd;
#pragma unroll
    for (int i = 0; i < 20; i++) {
        const int d = lane + 32 * i;
        dst[d] = roundtf((vals[i] - mean) * rstd * gg[d] + be[d]);
    }
}

// ---------------- launch ----------------
extern "C" void kernel_launch(void* const* d_in, const int* in_sizes, int n_in,
                              void* d_out, int out_size)
{
    (void)in_sizes; (void)n_in; (void)out_size;
    const float* hs   = (const float*)d_in[0];
    const float* enc  = (const float*)d_in[1];
    const float* Wq   = (const float*)d_in[2];
    const float* Wk   = (const float*)d_in[3];
    const float* Wv   = (const float*)d_in[4];
    const float* Wo   = (const float*)d_in[5];
    const float* bo   = (const float*)d_in[6];
    const float* ln0g = (const float*)d_in[7];
    const float* ln0b = (const float*)d_in[8];
    const float* d0W  = (const float*)d_in[9];
    const float* d0b  = (const float*)d_in[10];
    const float* u0W  = (const float*)d_in[11];
    const float* u0b  = (const float*)d_in[12];
    const float* ln1g = (const float*)d_in[13];
    const float* ln1b = (const float*)d_in[14];
    const float* d1W  = (const float*)d_in[15];
    const float* d1b  = (const float*)d_in[16];
    const float* u1W  = (const float*)d_in[17];
    const float* u1b  = (const float*)d_in[18];
    const float* sbr  = (const float*)d_in[19];
    const int*   idx0 = (const int*)d_in[20];
    const int*   idx1 = (const int*)d_in[21];
    float* out = (float*)d_out;

    float *pq, *pn1, *pk, *pv, *pF0, *pF1, *pA, *pW, *pb2;
    float *phsr, *pencr, *pwqr, *pwkr, *pwvr, *pdw0, *pdw1;
    cudaGetSymbolAddress((void**)&pq,   g_q);
    cudaGetSymbolAddress((void**)&pn1,  g_n1);
    cudaGetSymbolAddress((void**)&pk,   g_k);
    cudaGetSymbolAddress((void**)&pv,   g_v);
    cudaGetSymbolAddress((void**)&pF0,  g_F0);
    cudaGetSymbolAddress((void**)&pF1,  g_F1);
    cudaGetSymbolAddress((void**)&pA,   g_Abig);
    cudaGetSymbolAddress((void**)&pW,   g_Wbig);
    cudaGetSymbolAddress((void**)&pb2,  g_bo2);
    cudaGetSymbolAddress((void**)&phsr, g_hsr);
    cudaGetSymbolAddress((void**)&pencr,g_encr);
    cudaGetSymbolAddress((void**)&pwqr, g_wqr);
    cudaGetSymbolAddress((void**)&pwkr, g_wkr);
    cudaGetSymbolAddress((void**)&pwvr, g_wvr);
    cudaGetSymbolAddress((void**)&pdw0, g_dw0r);
    cudaGetSymbolAddress((void**)&pdw1, g_dw1r);

    const int att_smem = ATT_SMEM_FLOATS * (int)sizeof(float);
    cudaFuncSetAttribute(attn_kernel, cudaFuncAttributeMaxDynamicSharedMemorySize, att_smem);
    cudaFuncSetAttribute((const void*)gemm_tf32_kernel<0, true>,  cudaFuncAttributeMaxDynamicSharedMemorySize, GEMM_SMEM_BYTES);
    cudaFuncSetAttribute((const void*)gemm_tf32_kernel<0, false>, cudaFuncAttributeMaxDynamicSharedMemorySize, GEMM_SMEM_BYTES);
    cudaFuncSetAttribute((const void*)gemm_tf32_kernel<1, true>,  cudaFuncAttributeMaxDynamicSharedMemorySize, GEMM_SMEM_BYTES);
    cudaFuncSetAttribute((const void*)gemm_tf32_kernel<2, false>, cudaFuncAttributeMaxDynamicSharedMemorySize, GEMM_SMEM_BYTES);

    const int MKV = Bn * Tt;          // 616
    const int MQ  = Bn * Ss;          // 32768

    // 1) round all GEMM inputs to tf32 once
    round_kernel<<<1184, 256>>>(hs, phsr, enc, pencr, Wq, pwqr, Wk, pwkr,
                                Wv, pwvr, d0W, pdw0, d1W, pdw1);
    // 2) prep (fold up-proj weights through Wo; writes rounded Wbig)
    prep_kernel<<<Dd / PREP_E, 256>>>(Wo, u0W, u1W, u0b, u1b, bo, sbr, pW, pb2);

    // 3,4) K/V projections
    {
        dim3 grid(Dd / 128, (MKV + 127) / 128);
        gemm_tf32_kernel<0, false><<<grid, 256, GEMM_SMEM_BYTES>>>(pencr, pwkr, nullptr, pk, MKV, Dd, DEe, Dd);
        gemm_tf32_kernel<0, false><<<grid, 256, GEMM_SMEM_BYTES>>>(pencr, pwvr, nullptr, pv, MKV, Dd, DEe, Dd);
    }
    // 5) Q projection
    {
        dim3 grid(Dd / 128, MQ / 128);
        gemm_tf32_kernel<0, true><<<grid, 256, GEMM_SMEM_BYTES>>>(phsr, pwqr, nullptr, pq, MQ, Dd, Dd, Dd);
    }
    // 6) fused attention (F0, F1 raw; G rounded into Abig[:,0:640))
    {
        dim3 grid(Ss / ATT_QT, Bn * Hh);
        attn_kernel<<<grid, ATT_QT, att_smem>>>(pq, pk, pv, idx0, idx1, sbr, pF0, pF1, pA);
    }
    // 7) LayerNorm -> rounded n0 (reuses g_q), n1
    ln_kernel<<<2 * MQ / 8, 256>>>(pF0, pF1, ln0g, ln0b, ln1g, ln1b, pq, pn1);

    // 8,9) down-proj + bias + SiLU (rounded) into Abig cols [640,704),[704,768)
    {
        dim3 grid(1, MQ / 128);
        gemm_tf32_kernel<2, false><<<grid, 256, GEMM_SMEM_BYTES>>>(pq,  pdw0, d0b, pA + Dd,      MQ, Rr, Dd, KB);
        gemm_tf32_kernel<2, false><<<grid, 256, GEMM_SMEM_BYTES>>>(pn1, pdw1, d1b, pA + Dd + Rr, MQ, Rr, Dd, KB);
    }
    // 10) fused output GEMM: out = Abig x Wbig^T + bo2
    {
        dim3 grid(Dd / 128, MQ / 128);
        gemm_tf32_kernel<1, true><<<grid, 256, GEMM_SMEM_BYTES>>>(pA, pW, pb2, out, MQ, Dd, KB, Dd);
    }
}

// round 7
// speedup vs baseline: 1.6142x; 1.0053x over previous
#include <cuda_runtime.h>
#include <cstdint>

// Problem constants
constexpr int Bn  = 8;
constexpr int Ss  = 4096;
constexpr int Dd  = 640;
constexpr int Tt  = 77;
constexpr int DEe = 768;
constexpr int Hh  = 10;
constexpr int HDd = 64;
constexpr int Rr  = 64;
constexpr int KB  = 768;   // fused final-GEMM K = Dd + 2*Rr
constexpr float LN_EPS = 1e-5f;

// ---------------- scratch (static device globals; no allocation) ----------------
__device__ float g_q   [(size_t)Bn*Ss*Dd];   // Q proj; reused as n0 after attention
__device__ float g_n1  [(size_t)Bn*Ss*Dd];
__device__ float g_k   [(size_t)Bn*Tt*Dd];
__device__ float g_v   [(size_t)Bn*Tt*Dd];
__device__ float g_F0  [(size_t)Bn*Ss*Dd];
__device__ float g_F1  [(size_t)Bn*Ss*Dd];
__device__ float g_Abig[(size_t)Bn*Ss*KB];   // [G | h0 | h1]  (tf32-rounded)
__device__ float g_Wbig[(size_t)Dd*KB];      // [Wo | c1*M0 | c1*M1] (tf32-rounded)
__device__ float g_bo2 [Dd];
// tf32-pre-rounded GEMM inputs
__device__ float g_hsr [(size_t)Bn*Ss*Dd];
__device__ float g_encr[(size_t)Bn*Tt*DEe];
__device__ float g_wqr [(size_t)Dd*Dd];
__device__ float g_wkr [(size_t)Dd*DEe];
__device__ float g_wvr [(size_t)Dd*DEe];
__device__ float g_dw0r[(size_t)Rr*Dd];
__device__ float g_dw1r[(size_t)Rr*Dd];

__device__ __forceinline__ uint32_t f2tf32(float x) {
    uint32_t r;
    asm("cvt.rna.tf32.f32 %0, %1;" : "=r"(r) : "f"(x));
    return r;
}
__device__ __forceinline__ float roundtf(float x) { return __uint_as_float(f2tf32(x)); }

__device__ __forceinline__ void mma_tf32(float c[4], const uint32_t a[4], const uint32_t b[2]) {
    asm volatile(
        "mma.sync.aligned.m16n8k8.row.col.f32.tf32.tf32.f32 "
        "{%0,%1,%2,%3}, {%4,%5,%6,%7}, {%8,%9}, {%0,%1,%2,%3};"
        : "+f"(c[0]), "+f"(c[1]), "+f"(c[2]), "+f"(c[3])
        : "r"(a[0]), "r"(a[1]), "r"(a[2]), "r"(a[3]), "r"(b[0]), "r"(b[1]));
}

__device__ __forceinline__ void cp_async16(uint32_t dst, const void* src, bool pred) {
    const int nbytes = pred ? 16 : 0;
    asm volatile("cp.async.cg.shared.global [%0], [%1], 16, %2;"
                 :: "r"(dst), "l"(src), "r"(nbytes));
}
__device__ __forceinline__ void cp_commit() { asm volatile("cp.async.commit_group;"); }
__device__ __forceinline__ void cp_wait0()  { asm volatile("cp.async.wait_group 0;"); }

// ---------------- round inputs to tf32 (rna) once ----------------
__global__ void round_kernel(const float* __restrict__ hs,  float* __restrict__ hsr,
                             const float* __restrict__ enc, float* __restrict__ encr,
                             const float* __restrict__ Wq,  float* __restrict__ wqr,
                             const float* __restrict__ Wk,  float* __restrict__ wkr,
                             const float* __restrict__ Wv,  float* __restrict__ wvr,
                             const float* __restrict__ d0W, float* __restrict__ dw0r,
                             const float* __restrict__ d1W, float* __restrict__ dw1r)
{
    const long n_hs  = (long)Bn*Ss*Dd;
    const long n_enc = (long)Bn*Tt*DEe;
    const long n_wq  = (long)Dd*Dd;
    const long n_wk  = (long)Dd*DEe;
    const long n_dw  = (long)Rr*Dd;
    const long tot4 = (n_hs + n_enc + n_wq + 2*n_wk + 2*n_dw) / 4;
    for (long i4 = blockIdx.x * (long)blockDim.x + threadIdx.x; i4 < tot4;
         i4 += (long)gridDim.x * blockDim.x) {
        long i = i4 * 4;
        const float* s; float* d;
        if      (i < n_hs)                         { s = hs  + i;                     d = hsr  + i; }
        else if (i < n_hs+n_enc)                   { s = enc + (i-n_hs);              d = encr + (i-n_hs); }
        else if (i < n_hs+n_enc+n_wq)              { s = Wq  + (i-n_hs-n_enc);        d = wqr  + (i-n_hs-n_enc); }
        else if (i < n_hs+n_enc+n_wq+n_wk)         { s = Wk  + (i-n_hs-n_enc-n_wq);   d = wkr  + (i-n_hs-n_enc-n_wq); }
        else if (i < n_hs+n_enc+n_wq+2*n_wk)       { s = Wv  + (i-n_hs-n_enc-n_wq-n_wk); d = wvr + (i-n_hs-n_enc-n_wq-n_wk); }
        else if (i < n_hs+n_enc+n_wq+2*n_wk+n_dw)  { s = d0W + (i-n_hs-n_enc-n_wq-2*n_wk); d = dw0r + (i-n_hs-n_enc-n_wq-2*n_wk); }
        else                                       { s = d1W + (i-n_hs-n_enc-n_wq-2*n_wk-n_dw); d = dw1r + (i-n_hs-n_enc-n_wq-2*n_wk-n_dw); }
        float4 v = *(const float4*)s;
        v.x = roundtf(v.x); v.y = roundtf(v.y); v.z = roundtf(v.z); v.w = roundtf(v.w);
        *(float4*)d = v;
    }
}

// ================= TF32 GEMM (cp.async 2-stage ping-pong) =======================
constexpr int GLDA = 36;
constexpr int GEMM_STAGE = 128 * GLDA;
constexpr int GEMM_SMEM_BYTES = 2 * 2 * GEMM_STAGE * 4;  // 73728

// EPI: 0 = none, 1 = +bias, 2 = silu(acc+bias) rounded to tf32
template<int EPI, bool FULL>
__global__ __launch_bounds__(256, 2)
void gemm_tf32_kernel(const float* __restrict__ A, const float* __restrict__ W,
                      const float* __restrict__ bias, float* __restrict__ C,
                      int M, int N, int K, int ldc)
{
    extern __shared__ uint32_t smem_u[];
    uint32_t* AsBase = smem_u;
    uint32_t* BsBase = smem_u + GEMM_STAGE;
    const uint32_t smem_addr = (uint32_t)__cvta_generic_to_shared(smem_u);

    const int tid  = threadIdx.x;
    const int wid  = tid >> 5;
    const int lane = tid & 31;
    const int g    = lane >> 2;
    const int tg   = lane & 3;

    const int m0 = blockIdx.y * 128;
    const int n0 = blockIdx.x * 128;
    const int wm = (wid & 1) * 64;
    const int wn = (wid >> 1) * 32;

    const int ldrow = tid >> 3;
    const int ldseg = tid & 7;

    float acc[4][4][4];
#pragma unroll
    for (int i = 0; i < 4; i++)
#pragma unroll
        for (int j = 0; j < 4; j++)
#pragma unroll
            for (int r = 0; r < 4; r++) acc[i][j][r] = 0.f;

    auto stage_cp = [&](int k0, int stage) {
        const uint32_t abase = smem_addr + stage * (2 * GEMM_STAGE * 4);
        const uint32_t bbase = abase + GEMM_STAGE * 4;
#pragma unroll
        for (int p = 0; p < 4; p++) {
            const int row = ldrow + p * 32;
            const int gm = m0 + row;
            const int gn = n0 + row;
            const uint32_t soff = (row * GLDA + ldseg * 4) * 4;
            if (FULL) {
                cp_async16(abase + soff, A + (size_t)gm * K + k0 + ldseg * 4, true);
                cp_async16(bbase + soff, W + (size_t)gn * K + k0 + ldseg * 4, true);
            } else {
                const int gmc = gm < M ? gm : M - 1;
                const int gnc = gn < N ? gn : N - 1;
                cp_async16(abase + soff, A + (size_t)gmc * K + k0 + ldseg * 4, gm < M);
                cp_async16(bbase + soff, W + (size_t)gnc * K + k0 + ldseg * 4, gn < N);
            }
        }
        cp_commit();
    };

    stage_cp(0, 0);

    int cur = 0;
    for (int k0 = 0; k0 < K; k0 += 32) {
        cp_wait0();
        __syncthreads();

        if (k0 + 32 < K) stage_cp(k0 + 32, cur ^ 1);

        const uint32_t* As = AsBase + cur * (2 * GEMM_STAGE);
        const uint32_t* Bs = BsBase + cur * (2 * GEMM_STAGE);
#pragma unroll
        for (int ka = 0; ka < 4; ka++) {
            const int kc = ka * 8;
            uint32_t afr[4][4];
            uint32_t bfr[4][2];
#pragma unroll
            for (int i = 0; i < 4; i++) {
                const int r0 = wm + 16 * i + g;
                afr[i][0] = As[r0 * GLDA + kc + tg];
                afr[i][1] = As[(r0 + 8) * GLDA + kc + tg];
                afr[i][2] = As[r0 * GLDA + kc + tg + 4];
                afr[i][3] = As[(r0 + 8) * GLDA + kc + tg + 4];
            }
#pragma unroll
            for (int j = 0; j < 4; j++) {
                const int nrow = wn + 8 * j + g;
                bfr[j][0] = Bs[nrow * GLDA + kc + tg];
                bfr[j][1] = Bs[nrow * GLDA + kc + tg + 4];
            }
#pragma unroll
            for (int i = 0; i < 4; i++)
#pragma unroll
                for (int j = 0; j < 4; j++)
                    mma_tf32(acc[i][j], afr[i], bfr[j]);
        }
        cur ^= 1;
    }

#pragma unroll
    for (int i = 0; i < 4; i++) {
        const int rowA = m0 + wm + 16 * i + g;
        const int rowB = rowA + 8;
#pragma unroll
        for (int j = 0; j < 4; j++) {
            const int col = n0 + wn + 8 * j + 2 * tg;
            if (!FULL && col >= N) continue;
            float2 bv = make_float2(0.f, 0.f);
            if (EPI >= 1) bv = *(const float2*)(bias + col);
#pragma unroll
            for (int h = 0; h < 2; h++) {
                const int row = h ? rowB : rowA;
                if (!FULL && row >= M) continue;
                float x = acc[i][j][2 * h]     + bv.x;
                float y = acc[i][j][2 * h + 1] + bv.y;
                if (EPI == 2) {
                    x = roundtf(x / (1.f + expf(-x)));
                    y = roundtf(y / (1.f + expf(-y)));
                }
                *(float2*)(C + (size_t)row * ldc + col) = make_float2(x, y);
            }
        }
    }
}

// ---------------- prep: fold up-proj weights through Wo (exact fp32) ------------
constexpr int PREP_E = 8;
constexpr int PREP_DC = 64;

__global__ __launch_bounds__(256)
void prep_kernel(const float* __restrict__ Wo,
                 const float* __restrict__ u0W, const float* __restrict__ u1W,
                 const float* __restrict__ u0b, const float* __restrict__ u1b,
                 const float* __restrict__ bo,  const float* __restrict__ sbr,
                 float* __restrict__ Wbig, float* __restrict__ bo2)
{
    __shared__ float sWo[PREP_E][PREP_DC];
    __shared__ float su0[PREP_DC][Rr];
    __shared__ float su1[PREP_DC][Rr];

    const int tid = threadIdx.x;
    const int e0  = blockIdx.x * PREP_E;
    const int el  = tid >> 5;
    const int rl  = tid & 31;
    const float blend = 1.f / (1.f + expf(-*sbr));
    const float c1 = blend * (1.f / 3.f);

    float a00 = 0.f, a01 = 0.f, a10 = 0.f, a11 = 0.f;

    for (int d0 = 0; d0 < Dd; d0 += PREP_DC) {
        for (int i = tid; i < PREP_E * PREP_DC; i += 256) {
            const int e = i >> 6, d = i & 63;
            sWo[e][d] = Wo[(size_t)(e0 + e) * Dd + d0 + d];
        }
        for (int i = tid; i < PREP_DC * Rr; i += 256) {
            const int d = i >> 6, r = i & 63;
            su0[d][r] = u0W[(size_t)(d0 + d) * Rr + r];
            su1[d][r] = u1W[(size_t)(d0 + d) * Rr + r];
        }
        __syncthreads();
#pragma unroll 8
        for (int dd = 0; dd < PREP_DC; dd++) {
            const float w = sWo[el][dd];
            a00 = fmaf(w, su0[dd][rl],      a00);
            a01 = fmaf(w, su0[dd][rl + 32], a01);
            a10 = fmaf(w, su1[dd][rl],      a10);
            a11 = fmaf(w, su1[dd][rl + 32], a11);
        }
        __syncthreads();
    }

    const int e = e0 + el;
    {
        float* dst = Wbig + (size_t)e * KB;
        dst[Dd + rl]           = roundtf(c1 * a00);
        dst[Dd + rl + 32]      = roundtf(c1 * a01);
        dst[Dd + Rr + rl]      = roundtf(c1 * a10);
        dst[Dd + Rr + rl + 32] = roundtf(c1 * a11);
    }
    for (int i = tid; i < PREP_E * (Dd / 4); i += 256) {
        const int er = i / (Dd / 4);
        const int d4 = i % (Dd / 4);
        float4 v = *(const float4*)(Wo + (size_t)(e0 + er) * Dd + d4 * 4);
        v.x = roundtf(v.x); v.y = roundtf(v.y); v.z = roundtf(v.z); v.w = roundtf(v.w);
        *(float4*)(Wbig + (size_t)(e0 + er) * KB + d4 * 4) = v;
    }
    {
        float s = 0.f;
        for (int d = rl; d < Dd; d += 32)
            s = fmaf(Wo[(size_t)e * Dd + d], u0b[d] + u1b[d], s);
#pragma unroll
        for (int o = 16; o > 0; o >>= 1) s += __shfl_xor_sync(0xffffffffu, s, o);
        if (rl == 0) bo2[e] = bo[e] + c1 * s;
    }
}

// ---------------- tensor-core attention -----------------------------------------
// One block = 256 queries x one (b,h). QK^T and global P.V on mma.tf32
// (V split hi/lo for near-exact V). Entity paths scalar (near-fp32).
constexpr int AM  = 256;   // queries per block
constexpr int TP  = 80;    // padded T
constexpr int KS  = 68;    // K smem stride   (mod32 = 4 -> conflict-free B frags)
constexpr int VS  = 72;    // V smem stride   (mod32 = 8 -> conflict-free B frags)
constexpr int QS  = 68;    // Q smem stride   (A frags conflict-free)
constexpr int PS  = 84;    // P smem stride   (mod32 = 20 -> conflict-free A frags)
constexpr int ATT_SMEM_FLOATS = TP*KS + 2*TP*VS + AM*QS + AM*PS;  // 55872 -> 223488 B

__global__ __launch_bounds__(AM, 1)
void attn_kernel(const float* __restrict__ q, const float* __restrict__ k,
                 const float* __restrict__ v,
                 const int* __restrict__ idx0, const int* __restrict__ idx1,
                 const float* __restrict__ sbr,
                 float* __restrict__ F0, float* __restrict__ F1,
                 float* __restrict__ Abig)
{
    extern __shared__ float sm[];
    float* Ksh = sm;                    // [TP][KS]  (rounded tf32)
    float* Vh  = Ksh + TP * KS;         // [TP][VS]
    float* Vl  = Vh  + TP * VS;         // [TP][VS]
    float* Qsh = Vl  + TP * VS;         // [AM][QS]  (rounded, pre-scaled) -> later Gent
    float* Psh = Qsh + AM * QS;         // [AM][PS]  scores -> rounded exp p; col 80 = invz
    __shared__ int si0[8], si1[8];

    const int tid  = threadIdx.x;
    const int wid  = tid >> 5;
    const int lane = tid & 31;
    const int g    = lane >> 2;
    const int tg   = lane & 3;
    const int b    = blockIdx.y / Hh;
    const int h    = blockIdx.y % Hh;
    const int s0   = blockIdx.x * AM;

    if (tid < 8) { si0[tid] = idx0[tid]; si1[tid] = idx1[tid]; }

    const float blend = 1.f / (1.f + expf(-*sbr));
    const float c1 = blend * (1.f / 3.f);
    const float c2 = 1.f - 2.f * blend * (1.f / 3.f);

    // stage K (rounded), V (split hi/lo), zero-padded rows
    const float* kb = k + (size_t)b * Tt * Dd + h * HDd;
    const float* vb = v + (size_t)b * Tt * Dd + h * HDd;
    for (int i = tid; i < TP * HDd; i += AM) {
        const int t = i >> 6, d = i & 63;
        float kv = 0.f, vv = 0.f;
        if (t < Tt) { kv = kb[(size_t)t * Dd + d]; vv = vb[(size_t)t * Dd + d]; }
        Ksh[t * KS + d] = roundtf(kv);
        const float vh = roundtf(vv);
        Vh[t * VS + d] = vh;
        Vl[t * VS + d] = roundtf(vv - vh);
    }
    // stage Q (pre-scaled by 1/8, rounded)
    const float* qb = q + (size_t)(b * Ss + s0) * Dd + h * HDd;
    for (int i = tid; i < AM * HDd; i += AM) {
        const int r = i >> 6, d = i & 63;
        Qsh[r * QS + d] = roundtf(qb[(size_t)r * Dd + d] * 0.125f);
    }
    __syncthreads();

    // ---- QK^T mma: each warp does rows [wid*32, wid*32+32), all 10 n-tiles ----
    {
        float qacc[2][10][4];
#pragma unroll
        for (int i = 0; i < 2; i++)
#pragma unroll
            for (int j = 0; j < 10; j++)
#pragma unroll
                for (int r = 0; r < 4; r++) qacc[i][j][r] = 0.f;

#pragma unroll
        for (int ka = 0; ka < 8; ka++) {
            const int kc = ka * 8;
            uint32_t afr[2][4], bfr[10][2];
#pragma unroll
            for (int i = 0; i < 2; i++) {
                const int r0 = wid * 32 + 16 * i + g;
                afr[i][0] = __float_as_uint(Qsh[r0 * QS + kc + tg]);
                afr[i][1] = __float_as_uint(Qsh[(r0 + 8) * QS + kc + tg]);
                afr[i][2] = __float_as_uint(Qsh[r0 * QS + kc + tg + 4]);
                afr[i][3] = __float_as_uint(Qsh[(r0 + 8) * QS + kc + tg + 4]);
            }
#pragma unroll
            for (int j = 0; j < 10; j++) {
                const int t = 8 * j + g;
                bfr[j][0] = __float_as_uint(Ksh[t * KS + kc + tg]);
                bfr[j][1] = __float_as_uint(Ksh[t * KS + kc + tg + 4]);
            }
#pragma unroll
            for (int i = 0; i < 2; i++)
#pragma unroll
                for (int j = 0; j < 10; j++)
                    mma_tf32(qacc[i][j], afr[i], bfr[j]);
        }
        // store scores to Psh
#pragma unroll
        for (int i = 0; i < 2; i++) {
            const int rowA = wid * 32 + 16 * i + g;
#pragma unroll
            for (int j = 0; j < 10; j++) {
                const int col = 8 * j + 2 * tg;
                *(float2*)&Psh[rowA * PS + col]       = make_float2(qacc[i][j][0], qacc[i][j][1]);
                *(float2*)&Psh[(rowA + 8) * PS + col] = make_float2(qacc[i][j][2], qacc[i][j][3]);
            }
        }
    }
    __syncthreads();

    // ---- scalar phase: softmaxes, entity AVs, F0/F1, Gent -> Qsh ----
    {
        float* prow = &Psh[tid * PS];
        float e0s[8], e1s[8];
#pragma unroll
        for (int j = 0; j < 8; j++) { e0s[j] = prow[si0[j]]; e1s[j] = prow[si1[j]]; }

        float m = -1e30f;
        for (int t = 0; t < Tt; t++) m = fmaxf(m, prow[t]);
        float z = 0.f;
        for (int t = 0; t < Tt; t++) {
            const float p = expf(prow[t] - m);
            prow[t] = roundtf(p);       // rounded for PV mma
            z += p;
        }
        prow[77] = 0.f; prow[78] = 0.f; prow[79] = 0.f;
        prow[80] = 1.f / z;             // invz for PV combine

        float m0 = -1e30f, m1 = -1e30f;
#pragma unroll
        for (int j = 0; j < 8; j++) { m0 = fmaxf(m0, e0s[j]); m1 = fmaxf(m1, e1s[j]); }
        float z0 = 0.f, z1 = 0.f;
#pragma unroll
        for (int j = 0; j < 8; j++) {
            e0s[j] = expf(e0s[j] - m0); z0 += e0s[j];
            e1s[j] = expf(e1s[j] - m1); z1 += e1s[j];
        }
        const float rz0 = 1.f / z0, rz1 = 1.f / z1;
        const float iz0 = c1 / z0, iz1 = c1 / z1;

        const size_t fbase = (size_t)(b * Ss + s0 + tid) * Dd + h * HDd;

        float4 A0[16], A1[16];
#pragma unroll
        for (int i = 0; i < 16; i++) { A0[i] = make_float4(0,0,0,0); A1[i] = make_float4(0,0,0,0); }
#pragma unroll
        for (int j = 0; j < 8; j++) {
            const float p0 = e0s[j], p1 = e1s[j];
            const float4* vh0 = (const float4*)&Vh[si0[j] * VS];
            const float4* vl0 = (const float4*)&Vl[si0[j] * VS];
            const float4* vh1 = (const float4*)&Vh[si1[j] * VS];
            const float4* vl1 = (const float4*)&Vl[si1[j] * VS];
#pragma unroll
            for (int i = 0; i < 16; i++) {
                float4 v0h = vh0[i], v0l = vl0[i];
                float4 v1h = vh1[i], v1l = vl1[i];
                A0[i].x = fmaf(p0, v0h.x + v0l.x, A0[i].x);
                A0[i].y = fmaf(p0, v0h.y + v0l.y, A0[i].y);
                A0[i].z = fmaf(p0, v0h.z + v0l.z, A0[i].z);
                A0[i].w = fmaf(p0, v0h.w + v0l.w, A0[i].w);
                A1[i].x = fmaf(p1, v1h.x + v1l.x, A1[i].x);
                A1[i].y = fmaf(p1, v1h.y + v1l.y, A1[i].y);
                A1[i].z = fmaf(p1, v1h.z + v1l.z, A1[i].z);
                A1[i].w = fmaf(p1, v1h.w + v1l.w, A1[i].w);
            }
        }
        float4* of0 = (float4*)(F0 + fbase);
        float4* of1 = (float4*)(F1 + fbase);
        float* gdst = &Qsh[tid * QS];
#pragma unroll
        for (int i = 0; i < 16; i++) {
            of0[i] = make_float4(A0[i].x * rz0, A0[i].y * rz0, A0[i].z * rz0, A0[i].w * rz0);
            of1[i] = make_float4(A1[i].x * rz1, A1[i].y * rz1, A1[i].z * rz1, A1[i].w * rz1);
            float4 ge;
            ge.x = A0[i].x * iz0 + A1[i].x * iz1;
            ge.y = A0[i].y * iz0 + A1[i].y * iz1;
            ge.z = A0[i].z * iz0 + A1[i].z * iz1;
            ge.w = A0[i].w * iz0 + A1[i].w * iz1;
            *(float4*)(gdst + i * 4) = ge;
        }
    }
    __syncthreads();

    // ---- global P.V mma (two passes: Vh, Vl) + combine with Gent ----
    {
        float pacc[2][8][4];
#pragma unroll
        for (int i = 0; i < 2; i++)
#pragma unroll
            for (int j = 0; j < 8; j++)
#pragma unroll
                for (int r = 0; r < 4; r++) pacc[i][j][r] = 0.f;

#pragma unroll
        for (int ka = 0; ka < 10; ka++) {
            const int kc = ka * 8;
            uint32_t afr[2][4];
#pragma unroll
            for (int i = 0; i < 2; i++) {
                const int r0 = wid * 32 + 16 * i + g;
                afr[i][0] = __float_as_uint(Psh[r0 * PS + kc + tg]);
                afr[i][1] = __float_as_uint(Psh[(r0 + 8) * PS + kc + tg]);
                afr[i][2] = __float_as_uint(Psh[r0 * PS + kc + tg + 4]);
                afr[i][3] = __float_as_uint(Psh[(r0 + 8) * PS + kc + tg + 4]);
            }
#pragma unroll
            for (int j = 0; j < 8; j++) {
                const int n = 8 * j + g;
                uint32_t bh[2], bl[2];
                bh[0] = __float_as_uint(Vh[(kc + tg) * VS + n]);
                bh[1] = __float_as_uint(Vh[(kc + tg + 4) * VS + n]);
                bl[0] = __float_as_uint(Vl[(kc + tg) * VS + n]);
                bl[1] = __float_as_uint(Vl[(kc + tg + 4) * VS + n]);
#pragma unroll
                for (int i = 0; i < 2; i++) {
                    mma_tf32(pacc[i][j], afr[i], bh);
                    mma_tf32(pacc[i][j], afr[i], bl);
                }
            }
        }
        // combine: G = c2*invz*PV + Gent, write rounded into Abig
        const size_t gb = (size_t)(b * Ss + s0);
#pragma unroll
        for (int i = 0; i < 2; i++) {
            const int rowA = wid * 32 + 16 * i + g;
#pragma unroll
            for (int hh = 0; hh < 2; hh++) {
                const int row = rowA + 8 * hh;
                const float czr = c2 * Psh[row * PS + 80];
#pragma unroll
                for (int j = 0; j < 8; j++) {
                    const int col = 8 * j + 2 * tg;
                    float x = fmaf(pacc[i][j][2 * hh],     czr, Qsh[row * QS + col]);
                    float y = fmaf(pacc[i][j][2 * hh + 1], czr, Qsh[row * QS + col + 1]);
                    *(float2*)(Abig + (gb + row) * (size_t)KB + h * HDd + col) =
                        make_float2(roundtf(x), roundtf(y));
                }
            }
        }
    }
}

// ---------------- LayerNorm only: F0/F1 -> rounded n0/n1 -----------------------
__global__ __launch_bounds__(256)
void ln_kernel(const float* __restrict__ F0, const float* __restrict__ F1,
               const float* __restrict__ ln0g, const float* __restrict__ ln0b,
               const float* __restrict__ ln1g, const float* __restrict__ ln1b,
               float* __restrict__ n0, float* __restrict__ n1)
{
    const int wid  = threadIdx.x >> 5;
    const int lane = threadIdx.x & 31;
    const int task = blockIdx.x * 8 + wid;
    const int a    = task >= Bn * Ss;
    const int row  = a ? task - Bn * Ss : task;

    const float* src = (a ? F1 : F0) + (size_t)row * Dd;
    float vals[20];
    float sum = 0.f;
#pragma unroll
    for (int i = 0; i < 20; i++) { vals[i] = src[lane + 32 * i]; sum += vals[i]; }
#pragma unroll
    for (int o = 16; o > 0; o >>= 1) sum += __shfl_xor_sync(0xffffffffu, sum, o);
    const float mean = sum * (1.f / Dd);
    float vs = 0.f;
#pragma unroll
    for (int i = 0; i < 20; i++) { const float dv = vals[i] - mean; vs = fmaf(dv, dv, vs); }
#pragma unroll
    for (int o = 16; o > 0; o >>= 1) vs += __shfl_xor_sync(0xffffffffu, vs, o);
    const float rstd = rsqrtf(vs * (1.f / Dd) + LN_EPS);
    const float* gg = a ? ln1g : ln0g;
    const float* be = a ? ln1b : ln0b;
    float* dst = (a ? n1 : n0) + (size_t)row * Dd;
#pragma unroll
    for (int i = 0; i < 20; i++) {
        const int d = lane + 32 * i;
        dst[d] = roundtf((vals[i] - mean) * rstd * gg[d] + be[d]);
    }
}

// ---------------- launch ----------------
extern "C" void kernel_launch(void* const* d_in, const int* in_sizes, int n_in,
                              void* d_out, int out_size)
{
    (void)in_sizes; (void)n_in; (void)out_size;
    const float* hs   = (const float*)d_in[0];
    const float* enc  = (const float*)d_in[1];
    const float* Wq   = (const float*)d_in[2];
    const float* Wk   = (const float*)d_in[3];
    const float* Wv   = (const float*)d_in[4];
    const float* Wo   = (const float*)d_in[5];
    const float* bo   = (const float*)d_in[6];
    const float* ln0g = (const float*)d_in[7];
    const float* ln0b = (const float*)d_in[8];
    const float* d0W  = (const float*)d_in[9];
    const float* d0b  = (const float*)d_in[10];
    const float* u0W  = (const float*)d_in[11];
    const float* u0b  = (const float*)d_in[12];
    const float* ln1g = (const float*)d_in[13];
    const float* ln1b = (const float*)d_in[14];
    const float* d1W  = (const float*)d_in[15];
    const float* d1b  = (const float*)d_in[16];
    const float* u1W  = (const float*)d_in[17];
    const float* u1b  = (const float*)d_in[18];
    const float* sbr  = (const float*)d_in[19];
    const int*   idx0 = (const int*)d_in[20];
    const int*   idx1 = (const int*)d_in[21];
    float* out = (float*)d_out;

    float *pq, *pn1, *pk, *pv, *pF0, *pF1, *pA, *pW, *pb2;
    float *phsr, *pencr, *pwqr, *pwkr, *pwvr, *pdw0, *pdw1;
    cudaGetSymbolAddress((void**)&pq,   g_q);
    cudaGetSymbolAddress((void**)&pn1,  g_n1);
    cudaGetSymbolAddress((void**)&pk,   g_k);
    cudaGetSymbolAddress((void**)&pv,   g_v);
    cudaGetSymbolAddress((void**)&pF0,  g_F0);
    cudaGetSymbolAddress((void**)&pF1,  g_F1);
    cudaGetSymbolAddress((void**)&pA,   g_Abig);
    cudaGetSymbolAddress((void**)&pW,   g_Wbig);
    cudaGetSymbolAddress((void**)&pb2,  g_bo2);
    cudaGetSymbolAddress((void**)&phsr, g_hsr);
    cudaGetSymbolAddress((void**)&pencr,g_encr);
    cudaGetSymbolAddress((void**)&pwqr, g_wqr);
    cudaGetSymbolAddress((void**)&pwkr, g_wkr);
    cudaGetSymbolAddress((void**)&pwvr, g_wvr);
    cudaGetSymbolAddress((void**)&pdw0, g_dw0r);
    cudaGetSymbolAddress((void**)&pdw1, g_dw1r);

    const int att_smem = ATT_SMEM_FLOATS * (int)sizeof(float);
    cudaFuncSetAttribute(attn_kernel, cudaFuncAttributeMaxDynamicSharedMemorySize, att_smem);
    cudaFuncSetAttribute((const void*)gemm_tf32_kernel<0, true>,  cudaFuncAttributeMaxDynamicSharedMemorySize, GEMM_SMEM_BYTES);
    cudaFuncSetAttribute((const void*)gemm_tf32_kernel<0, false>, cudaFuncAttributeMaxDynamicSharedMemorySize, GEMM_SMEM_BYTES);
    cudaFuncSetAttribute((const void*)gemm_tf32_kernel<1, true>,  cudaFuncAttributeMaxDynamicSharedMemorySize, GEMM_SMEM_BYTES);
    cudaFuncSetAttribute((const void*)gemm_tf32_kernel<2, false>, cudaFuncAttributeMaxDynamicSharedMemorySize, GEMM_SMEM_BYTES);

    const int MKV = Bn * Tt;          // 616
    const int MQ  = Bn * Ss;          // 32768

    // 1) round all GEMM inputs to tf32 once
    round_kernel<<<1184, 256>>>(hs, phsr, enc, pencr, Wq, pwqr, Wk, pwkr,
                                Wv, pwvr, d0W, pdw0, d1W, pdw1);
    // 2) prep
    prep_kernel<<<Dd / PREP_E, 256>>>(Wo, u0W, u1W, u0b, u1b, bo, sbr, pW, pb2);

    // 3,4) K/V projections
    {
        dim3 grid(Dd / 128, (MKV + 127) / 128);
        gemm_tf32_kernel<0, false><<<grid, 256, GEMM_SMEM_BYTES>>>(pencr, pwkr, nullptr, pk, MKV, Dd, DEe, Dd);
        gemm_tf32_kernel<0, false><<<grid, 256, GEMM_SMEM_BYTES>>>(pencr, pwvr, nullptr, pv, MKV, Dd, DEe, Dd);
    }
    // 5) Q projection
    {
        dim3 grid(Dd / 128, MQ / 128);
        gemm_tf32_kernel<0, true><<<grid, 256, GEMM_SMEM_BYTES>>>(phsr, pwqr, nullptr, pq, MQ, Dd, Dd, Dd);
    }
    // 6) tensor-core attention
    {
        dim3 grid(Ss / AM, Bn * Hh);
        attn_kernel<<<grid, AM, att_smem>>>(pq, pk, pv, idx0, idx1, sbr, pF0, pF1, pA);
    }
    // 7) LayerNorm -> rounded n0 (reuses g_q), n1
    ln_kernel<<<2 * MQ / 8, 256>>>(pF0, pF1, ln0g, ln0b, ln1g, ln1b, pq, pn1);

    // 8,9) down-proj + bias + SiLU
    {
        dim3 grid(1, MQ / 128);
        gemm_tf32_kernel<2, false><<<grid, 256, GEMM_SMEM_BYTES>>>(pq,  pdw0, d0b, pA + Dd,      MQ, Rr, Dd, KB);
        gemm_tf32_kernel<2, false><<<grid, 256, GEMM_SMEM_BYTES>>>(pn1, pdw1, d1b, pA + Dd + Rr, MQ, Rr, Dd, KB);
    }
    // 10) fused output GEMM
    {
        dim3 grid(Dd / 128, MQ / 128);
        gemm_tf32_kernel<1, true><<<grid, 256, GEMM_SMEM_BYTES>>>(pA, pW, pb2, out, MQ, Dd, KB, Dd);
    }
}